// round 1
// baseline (speedup 1.0000x reference)
#include <cuda_runtime.h>
#include <cuda_bf16.h>

// Problem constants (LearntNeighbourhoodSamplingV2: B=2, C=128, H=800, W=640, N=10000)
#define BB 2
#define CC 128
#define HH 800
#define WW 640
#define NN 10000

// Scratch: neighbor coordinates for k=1..8 (stored as gx,gy pairs, already clipped)
__device__ float2 g_coords[BB * NN * 8];

__device__ __forceinline__ float clampf(float v, float lo, float hi) {
    return fminf(fmaxf(v, lo), hi);
}

// Kernel 1: center sample (all 128 channels), 18-wide GEMM -> deltas -> neighbor coords.
// Writes out[b,n,c] = center_sample/9 (neighbor 0 contribution).
__global__ void __launch_bounds__(128) k_center(
    const float* __restrict__ img,
    const float* __restrict__ verts,
    const float* __restrict__ cw,
    const float* __restrict__ cb,
    float* __restrict__ out)
{
    const int p = blockIdx.x;          // 0 .. B*N-1
    const int b = p / NN;
    const int c = threadIdx.x;         // channel

    __shared__ float sf[CC];
    __shared__ float sd[18];

    const float vx = verts[p * 2 + 0];
    const float vy = verts[p * 2 + 1];

    float gx = clampf((vx + 1.0f) * 0.5f * (WW - 1), 0.0f, (float)(WW - 1));
    float gy = clampf((vy + 1.0f) * 0.5f * (HH - 1), 0.0f, (float)(HH - 1));
    int x0 = (int)floorf(gx);
    int y0 = (int)floorf(gy);
    int x1 = min(x0 + 1, WW - 1);
    int y1 = min(y0 + 1, HH - 1);
    float wx1 = gx - (float)x0;
    float wy1 = gy - (float)y0;
    float wx0 = 1.0f - wx1;
    float wy0 = 1.0f - wy1;

    const float* __restrict__ ip = img + (size_t)(b * CC + c) * (HH * WW);
    const int r0 = y0 * WW, r1 = y1 * WW;
    float v00 = __ldg(ip + r0 + x0);
    float v01 = __ldg(ip + r0 + x1);
    float v10 = __ldg(ip + r1 + x0);
    float v11 = __ldg(ip + r1 + x1);

    float f = v00 * wy0 * wx0 + v01 * wy0 * wx1 + v10 * wy1 * wx0 + v11 * wy1 * wx1;

    out[(size_t)p * CC + c] = f * (1.0f / 9.0f);
    sf[c] = f;
    __syncthreads();

    if (c < 18) {
        float acc = cb[c];
        const float* __restrict__ w = cw + c * CC;
        #pragma unroll 8
        for (int i = 0; i < CC; i++) acc = fmaf(sf[i], w[i], acc);
        sd[c] = acc;
    }
    __syncthreads();

    if (c >= 1 && c < 9) {
        const int k = c;  // neighbor 1..8
        float nx = vx + sd[2 * k];
        float ny = vy + sd[2 * k + 1];
        float ggx = clampf((nx + 1.0f) * 0.5f * (WW - 1), 0.0f, (float)(WW - 1));
        float ggy = clampf((ny + 1.0f) * 0.5f * (HH - 1), 0.0f, (float)(HH - 1));
        g_coords[p * 8 + (k - 1)] = make_float2(ggx, ggy);
    }
}

// Kernel 2: gather the 8 neighbor samples per (point, channel), accumulate mean.
__global__ void __launch_bounds__(128) k_neigh(
    const float* __restrict__ img,
    float* __restrict__ out)
{
    const int p = blockIdx.x;          // 0 .. B*N-1
    const int b = p / NN;
    const int c = threadIdx.x;         // channel

    __shared__ float2 sc[8];
    if (c < 8) sc[c] = g_coords[p * 8 + c];
    __syncthreads();

    const float* __restrict__ ip = img + (size_t)(b * CC + c) * (HH * WW);

    float acc = 0.0f;
    #pragma unroll
    for (int k = 0; k < 8; k++) {
        const float gx = sc[k].x;
        const float gy = sc[k].y;
        int x0 = (int)floorf(gx);
        int y0 = (int)floorf(gy);
        int x1 = min(x0 + 1, WW - 1);
        int y1 = min(y0 + 1, HH - 1);
        float wx1 = gx - (float)x0;
        float wy1 = gy - (float)y0;
        float wx0 = 1.0f - wx1;
        float wy0 = 1.0f - wy1;
        const int r0 = y0 * WW, r1 = y1 * WW;
        float v00 = __ldg(ip + r0 + x0);
        float v01 = __ldg(ip + r0 + x1);
        float v10 = __ldg(ip + r1 + x0);
        float v11 = __ldg(ip + r1 + x1);
        acc += v00 * wy0 * wx0 + v01 * wy0 * wx1 + v10 * wy1 * wx0 + v11 * wy1 * wx1;
    }

    const size_t o = (size_t)p * CC + c;
    out[o] = out[o] + acc * (1.0f / 9.0f);
}

extern "C" void kernel_launch(void* const* d_in, const int* in_sizes, int n_in,
                              void* d_out, int out_size)
{
    const float* img   = (const float*)d_in[0];   // (B, C, H, W)
    const float* verts = (const float*)d_in[1];   // (B, N, 2)
    const float* cw    = (const float*)d_in[2];   // (18, C)
    const float* cb    = (const float*)d_in[3];   // (18,)
    float* out = (float*)d_out;                   // (B, N, C)

    const int P = BB * NN;
    k_center<<<P, 128>>>(img, verts, cw, cb, out);
    k_neigh<<<P, 128>>>(img, out);
}

// round 2
// speedup vs baseline: 1.9852x; 1.9852x over previous
#include <cuda_runtime.h>
#include <cuda_bf16.h>

// Problem constants (B=2, C=128, H=800, W=640, N=10000)
#define BB 2
#define CC 128
#define HH 800
#define WW 640
#define NN 10000
#define HW (HH * WW)          // 512000

// Scratch: image transposed to (B, H, W, C) so one tap = 512 contiguous bytes.
__device__ float g_timg[(size_t)BB * HW * CC];   // 524 MB

__device__ __forceinline__ float clampf(float v, float lo, float hi) {
    return fminf(fmaxf(v, lo), hi);
}

// ---------------------------------------------------------------------------
// Transpose (B,C,H,W) -> (B,H,W,C). Tiled 32x32 via shared memory.
// grid = (HW/32, C/32, B), block = (32, 8)
// ---------------------------------------------------------------------------
__global__ void __launch_bounds__(256) k_transpose(const float* __restrict__ img)
{
    __shared__ float tile[32][33];
    const int b   = blockIdx.z;
    const int c0  = blockIdx.y * 32;
    const int hw0 = blockIdx.x * 32;
    const int tx = threadIdx.x, ty = threadIdx.y;

    const float* __restrict__ src = img + ((size_t)b * CC + c0) * HW + hw0;
    #pragma unroll
    for (int j = 0; j < 32; j += 8)
        tile[ty + j][tx] = src[(size_t)(ty + j) * HW + tx];
    __syncthreads();

    float* __restrict__ dst = g_timg + ((size_t)b * HW + hw0) * CC + c0;
    #pragma unroll
    for (int j = 0; j < 32; j += 8)
        dst[(size_t)(ty + j) * CC + tx] = tile[tx][ty + j];
}

// ---------------------------------------------------------------------------
// Fused sampler: one block per point, thread = channel.
//  1) center bilinear sample (coalesced from g_timg)
//  2) 18-wide dot with conv_w -> deltas
//  3) 8 neighbor coords -> tap offsets + weights in smem
//  4) 8 neighbor bilinear gathers, mean, single coalesced store
// ---------------------------------------------------------------------------
__global__ void __launch_bounds__(128) k_sample(
    const float* __restrict__ verts,
    const float* __restrict__ cw,
    const float* __restrict__ cb,
    float* __restrict__ out)
{
    const int p = blockIdx.x;            // 0 .. B*N-1
    const int b = p / NN;
    const int c = threadIdx.x;           // channel

    __shared__ float sf[CC];
    __shared__ float sd[18];
    __shared__ int   soff[8][4];
    __shared__ float sw[8][4];

    const float vx = verts[p * 2 + 0];
    const float vy = verts[p * 2 + 1];

    const float* __restrict__ tb = g_timg + (size_t)b * HW * CC;

    // ---- center sample ----
    float gx = clampf((vx + 1.0f) * 0.5f * (WW - 1), 0.0f, (float)(WW - 1));
    float gy = clampf((vy + 1.0f) * 0.5f * (HH - 1), 0.0f, (float)(HH - 1));
    int x0 = (int)floorf(gx);
    int y0 = (int)floorf(gy);
    int x1 = min(x0 + 1, WW - 1);
    int y1 = min(y0 + 1, HH - 1);
    float wx1 = gx - (float)x0, wy1 = gy - (float)y0;
    float wx0 = 1.0f - wx1,     wy0 = 1.0f - wy1;

    int o00 = (y0 * WW + x0) * CC;
    int o01 = (y0 * WW + x1) * CC;
    int o10 = (y1 * WW + x0) * CC;
    int o11 = (y1 * WW + x1) * CC;

    float f = tb[o00 + c] * (wy0 * wx0) + tb[o01 + c] * (wy0 * wx1)
            + tb[o10 + c] * (wy1 * wx0) + tb[o11 + c] * (wy1 * wx1);

    sf[c] = f;
    __syncthreads();

    // ---- 18-wide dot ----
    if (c < 18) {
        float acc = cb[c];
        const float* __restrict__ w = cw + c * CC;
        #pragma unroll 8
        for (int i = 0; i < CC; i++) acc = fmaf(sf[i], w[i], acc);
        sd[c] = acc;
    }
    __syncthreads();

    // ---- neighbor coords -> offsets + weights ----
    if (c < 8) {
        const int k = c + 1;             // neighbor 1..8 (0 is the center)
        float nx = vx + sd[2 * k];
        float ny = vy + sd[2 * k + 1];
        float ggx = clampf((nx + 1.0f) * 0.5f * (WW - 1), 0.0f, (float)(WW - 1));
        float ggy = clampf((ny + 1.0f) * 0.5f * (HH - 1), 0.0f, (float)(HH - 1));
        int nx0 = (int)floorf(ggx);
        int ny0 = (int)floorf(ggy);
        int nx1 = min(nx0 + 1, WW - 1);
        int ny1 = min(ny0 + 1, HH - 1);
        float nwx1 = ggx - (float)nx0, nwy1 = ggy - (float)ny0;
        float nwx0 = 1.0f - nwx1,      nwy0 = 1.0f - nwy1;
        soff[c][0] = (ny0 * WW + nx0) * CC;
        soff[c][1] = (ny0 * WW + nx1) * CC;
        soff[c][2] = (ny1 * WW + nx0) * CC;
        soff[c][3] = (ny1 * WW + nx1) * CC;
        sw[c][0] = nwy0 * nwx0;
        sw[c][1] = nwy0 * nwx1;
        sw[c][2] = nwy1 * nwx0;
        sw[c][3] = nwy1 * nwx1;
    }
    __syncthreads();

    // ---- 8 neighbor gathers ----
    float acc = f;
    #pragma unroll
    for (int k = 0; k < 8; k++) {
        int a0 = soff[k][0], a1 = soff[k][1], a2 = soff[k][2], a3 = soff[k][3];
        float w0 = sw[k][0], w1 = sw[k][1], w2 = sw[k][2], w3 = sw[k][3];
        acc += tb[a0 + c] * w0 + tb[a1 + c] * w1 + tb[a2 + c] * w2 + tb[a3 + c] * w3;
    }

    out[(size_t)p * CC + c] = acc * (1.0f / 9.0f);
}

extern "C" void kernel_launch(void* const* d_in, const int* in_sizes, int n_in,
                              void* d_out, int out_size)
{
    const float* img   = (const float*)d_in[0];   // (B, C, H, W)
    const float* verts = (const float*)d_in[1];   // (B, N, 2)
    const float* cw    = (const float*)d_in[2];   // (18, C)
    const float* cb    = (const float*)d_in[3];   // (18,)
    float* out = (float*)d_out;                   // (B, N, C)

    dim3 tgrid(HW / 32, CC / 32, BB);
    dim3 tblk(32, 8);
    k_transpose<<<tgrid, tblk>>>(img);

    k_sample<<<BB * NN, 128>>>(verts, cw, cb, out);
}